// round 4
// baseline (speedup 1.0000x reference)
#include <cuda_runtime.h>
#include <cstdint>

#define NL 6
#define NH 16
#define EE 1024
#define VV 32
#define NN 4096
#define HVD 512     // NH*VV
#define FFD 2048    // 2*EE

// ---------------- scratch (device globals; allocation-free) ----------------
__device__ float g_z[NN * EE];        // residual stream          16 MB
__device__ float g_q[NH * NN * VV];   // Q  [H][N][V]              8 MB
__device__ float g_k[NH * NN * VV];   // K                         8 MB
__device__ float g_v[NH * NN * VV];   // V                         8 MB
__device__ float g_o[NN * HVD];       // attn out [N][H*V]         8 MB
__device__ float g_an[NN * EE];       // post-attn LN             16 MB
__device__ float g_ff[NN * FFD];      // FF hidden                32 MB

// ---------------- fast exp on FMA pipe (avoids MUFU bottleneck) ------------
// exp(x) for x <= 0 (softmax args). 2^t split into int + degree-6 poly.
// Max rel err ~2e-5.
__device__ __forceinline__ float fexp(float x) {
    float t = fmaxf(x * 1.4426950408889634f, -126.0f);
    float fi = floorf(t);
    float f = t - fi;
    float p = 1.5403530e-4f;
    p = fmaf(p, f, 1.3333558e-3f);
    p = fmaf(p, f, 9.6181291e-3f);
    p = fmaf(p, f, 5.5504109e-2f);
    p = fmaf(p, f, 2.4022651e-1f);
    p = fmaf(p, f, 6.9314718e-1f);
    p = fmaf(p, f, 1.0f);
    return p * __int_as_float(((int)fi + 127) << 23);
}

// ---------------- embedding: z0 = table[context] + pos ---------------------
__global__ void __launch_bounds__(256) embed_kernel(const int* __restrict__ ctx,
                                                    const float* __restrict__ table,
                                                    const float* __restrict__ pos) {
    int idx = blockIdx.x * 256 + threadIdx.x;   // float4 index over N*E/4
    int n = idx >> 8;                            // E/4 = 256 float4 per row
    int e4 = idx & 255;
    int tok = ctx[n];
    float4 a = ((const float4*)table)[(size_t)tok * 256 + e4];
    float4 b = ((const float4*)pos)[idx];
    a.x += b.x; a.y += b.y; a.z += b.z; a.w += b.w;
    ((float4*)g_z)[idx] = a;
}

// ---------------- generic tiled GEMM (64x64x16, 256 thr, 4x4/thread) -------
// MODE 0: QKV   -> B layout [H][E][V], C layout [H][N][V]
// MODE 1: Wo    -> C = resid + A*B
// MODE 2: FF1   -> C = leaky_relu(A*B + bias, 0.01)
// MODE 3: FF2   -> C = resid + A*B + bias
template <int MODE>
__global__ void __launch_bounds__(256) gemm_kernel(const float* __restrict__ A,
                                                   const float* __restrict__ B,
                                                   const float* __restrict__ bias,
                                                   const float* __restrict__ resid,
                                                   float* __restrict__ C,
                                                   int M, int K, int NC) {
    __shared__ float As[16][65];
    __shared__ float Bs[16][64];
    const int t  = threadIdx.x;
    const int tx = t & 15, ty = t >> 4;
    const int row0 = blockIdx.y << 6, col0 = blockIdx.x << 6;

    const int am = t >> 2, ak = (t & 3) << 2;        // A tile: 64 rows x 16 k
    const int bk = t >> 4, bn = (t & 15) << 2;       // B tile: 16 k x 64 cols

    const float* Aptr = A + (size_t)(row0 + am) * K + ak;
    const float* Bptr;
    if (MODE == 0) {
        int col = col0 + bn;
        Bptr = B + (size_t)(col >> 5) * K * 32 + (size_t)bk * 32 + (col & 31);
    } else {
        Bptr = B + (size_t)bk * NC + col0 + bn;
    }

    float acc[4][4];
#pragma unroll
    for (int i = 0; i < 4; i++)
#pragma unroll
        for (int j = 0; j < 4; j++) acc[i][j] = 0.f;

    for (int kt = 0; kt < K; kt += 16) {
        float4 av = *(const float4*)(Aptr + kt);
        float4 bv;
        if (MODE == 0) bv = *(const float4*)(Bptr + (size_t)kt * 32);
        else           bv = *(const float4*)(Bptr + (size_t)kt * NC);

        As[ak + 0][am] = av.x;
        As[ak + 1][am] = av.y;
        As[ak + 2][am] = av.z;
        As[ak + 3][am] = av.w;
        *(float4*)&Bs[bk][bn] = bv;
        __syncthreads();

#pragma unroll
        for (int k = 0; k < 16; k++) {
            float a0 = As[k][ty * 4 + 0];
            float a1 = As[k][ty * 4 + 1];
            float a2 = As[k][ty * 4 + 2];
            float a3 = As[k][ty * 4 + 3];
            float4 b = *(const float4*)&Bs[k][tx * 4];
            acc[0][0] = fmaf(a0, b.x, acc[0][0]);
            acc[0][1] = fmaf(a0, b.y, acc[0][1]);
            acc[0][2] = fmaf(a0, b.z, acc[0][2]);
            acc[0][3] = fmaf(a0, b.w, acc[0][3]);
            acc[1][0] = fmaf(a1, b.x, acc[1][0]);
            acc[1][1] = fmaf(a1, b.y, acc[1][1]);
            acc[1][2] = fmaf(a1, b.z, acc[1][2]);
            acc[1][3] = fmaf(a1, b.w, acc[1][3]);
            acc[2][0] = fmaf(a2, b.x, acc[2][0]);
            acc[2][1] = fmaf(a2, b.y, acc[2][1]);
            acc[2][2] = fmaf(a2, b.z, acc[2][2]);
            acc[2][3] = fmaf(a2, b.w, acc[2][3]);
            acc[3][0] = fmaf(a3, b.x, acc[3][0]);
            acc[3][1] = fmaf(a3, b.y, acc[3][1]);
            acc[3][2] = fmaf(a3, b.z, acc[3][2]);
            acc[3][3] = fmaf(a3, b.w, acc[3][3]);
        }
        __syncthreads();
    }

#pragma unroll
    for (int i = 0; i < 4; i++) {
        int r = row0 + ty * 4 + i;
#pragma unroll
        for (int j = 0; j < 4; j++) {
            int c = col0 + tx * 4 + j;
            float val = acc[i][j];
            if (MODE == 0) {
                C[((size_t)(c >> 5) * M + r) * 32 + (c & 31)] = val;
            } else if (MODE == 1) {
                size_t o = (size_t)r * NC + c;
                C[o] = resid[o] + val;
            } else if (MODE == 2) {
                float x = val + bias[c];
                C[(size_t)r * NC + c] = x > 0.f ? x : 0.01f * x;
            } else {
                size_t o = (size_t)r * NC + c;
                C[o] = resid[o] + bias[c] + val;
            }
        }
    }
}

// ---------------- flash attention (per head, online softmax) ---------------
// Q,K,V: [H][N][32].  O: [N][H*32].  Block: 128 queries of one head.
__global__ void __launch_bounds__(128) attn_kernel(const float* __restrict__ Q,
                                                   const float* __restrict__ K,
                                                   const float* __restrict__ V,
                                                   float* __restrict__ O) {
    __shared__ float Ks[128 * 32];
    __shared__ float Vs[128 * 32];
    const int h = blockIdx.y;
    const int q0 = blockIdx.x << 7;
    const int tid = threadIdx.x;

    const float* Qp = Q + ((size_t)h * NN + q0 + tid) * VV;
    float q[32];
#pragma unroll
    for (int d4 = 0; d4 < 8; d4++) {
        float4 qv = *(const float4*)(Qp + d4 * 4);
        const float sc = 0.17677669529663687f;   // 1/sqrt(32)
        q[d4 * 4 + 0] = qv.x * sc;
        q[d4 * 4 + 1] = qv.y * sc;
        q[d4 * 4 + 2] = qv.z * sc;
        q[d4 * 4 + 3] = qv.w * sc;
    }

    float m = -1e30f, l = 0.f;
    float acc[32];
#pragma unroll
    for (int d = 0; d < 32; d++) acc[d] = 0.f;

    const float4* K4 = (const float4*)(K + (size_t)h * NN * VV);
    const float4* V4 = (const float4*)(V + (size_t)h * NN * VV);

    for (int kt = 0; kt < NN; kt += 128) {
        __syncthreads();
        const float4* Kt = K4 + (size_t)kt * 8;  // 8 float4 per 32-float row
        const float4* Vt = V4 + (size_t)kt * 8;
#pragma unroll
        for (int i = 0; i < 8; i++) {
            ((float4*)Ks)[tid + i * 128] = Kt[tid + i * 128];
            ((float4*)Vs)[tid + i * 128] = Vt[tid + i * 128];
        }
        __syncthreads();

#pragma unroll 1
        for (int jc = 0; jc < 128; jc += 16) {
            float s[16];
#pragma unroll
            for (int j = 0; j < 16; j++) {
                float a0 = 0.f, a1 = 0.f, a2 = 0.f, a3 = 0.f;
                const float* kr = Ks + (jc + j) * 32;
#pragma unroll
                for (int d4 = 0; d4 < 8; d4++) {
                    float4 kk = *(const float4*)(kr + d4 * 4);
                    a0 = fmaf(q[d4 * 4 + 0], kk.x, a0);
                    a1 = fmaf(q[d4 * 4 + 1], kk.y, a1);
                    a2 = fmaf(q[d4 * 4 + 2], kk.z, a2);
                    a3 = fmaf(q[d4 * 4 + 3], kk.w, a3);
                }
                s[j] = (a0 + a1) + (a2 + a3);
            }
            float cmax = s[0];
#pragma unroll
            for (int j = 1; j < 16; j++) cmax = fmaxf(cmax, s[j]);
            float mn = fmaxf(m, cmax);
            float corr = fexp(m - mn);
            m = mn;
            l *= corr;
#pragma unroll
            for (int d = 0; d < 32; d++) acc[d] *= corr;
#pragma unroll
            for (int j = 0; j < 16; j++) {
                float p = fexp(s[j] - mn);
                l += p;
                const float* vr = Vs + (jc + j) * 32;
#pragma unroll
                for (int d4 = 0; d4 < 8; d4++) {
                    float4 vv = *(const float4*)(vr + d4 * 4);
                    acc[d4 * 4 + 0] = fmaf(p, vv.x, acc[d4 * 4 + 0]);
                    acc[d4 * 4 + 1] = fmaf(p, vv.y, acc[d4 * 4 + 1]);
                    acc[d4 * 4 + 2] = fmaf(p, vv.z, acc[d4 * 4 + 2]);
                    acc[d4 * 4 + 3] = fmaf(p, vv.w, acc[d4 * 4 + 3]);
                }
            }
        }
    }

    float inv = 1.f / l;
    float* Op = O + (size_t)(q0 + tid) * HVD + h * VV;
#pragma unroll
    for (int d4 = 0; d4 < 8; d4++) {
        float4 ov;
        ov.x = acc[d4 * 4 + 0] * inv;
        ov.y = acc[d4 * 4 + 1] * inv;
        ov.z = acc[d4 * 4 + 2] * inv;
        ov.w = acc[d4 * 4 + 3] * inv;
        *(float4*)(Op + d4 * 4) = ov;
    }
}

// ---------------- layernorm: dim=1, unbiased std (ddof=1), no eps ----------
__device__ __forceinline__ float block_sum256(float v, float* sbuf) {
    int lane = threadIdx.x & 31, w = threadIdx.x >> 5;
#pragma unroll
    for (int o = 16; o > 0; o >>= 1) v += __shfl_xor_sync(0xffffffffu, v, o);
    if (lane == 0) sbuf[w] = v;
    __syncthreads();
    if (w == 0) {
        float x = (lane < 8) ? sbuf[lane] : 0.f;
#pragma unroll
        for (int o = 4; o > 0; o >>= 1) x += __shfl_xor_sync(0xffffffffu, x, o);
        if (lane == 0) sbuf[0] = x;
    }
    __syncthreads();
    float r = sbuf[0];
    __syncthreads();
    return r;
}

__global__ void __launch_bounds__(256) ln_kernel(float* __restrict__ X) {
    __shared__ float sbuf[8];
    const int tid = threadIdx.x;
    float* x = X + (size_t)blockIdx.x * EE;
    float v[4];
#pragma unroll
    for (int i = 0; i < 4; i++) v[i] = x[tid + i * 256];
    float s = (v[0] + v[1]) + (v[2] + v[3]);
    s = block_sum256(s, sbuf);
    float mean = s * (1.f / 1024.f);
    float ss = 0.f;
#pragma unroll
    for (int i = 0; i < 4; i++) {
        float d = v[i] - mean;
        ss = fmaf(d, d, ss);
    }
    ss = block_sum256(ss, sbuf);
    float inv = rsqrtf(ss * (1.f / 1023.f));
#pragma unroll
    for (int i = 0; i < 4; i++) x[tid + i * 256] = (v[i] - mean) * inv;
}

// ---------------- launch ---------------------------------------------------
extern "C" void kernel_launch(void* const* d_in, const int* in_sizes, int n_in,
                              void* d_out, int out_size) {
    const int*   ctx   = (const int*)d_in[0];
    const float* table = (const float*)d_in[1];
    const float* pos   = (const float*)d_in[2];
    const float* Wq    = (const float*)d_in[3];
    const float* Wk    = (const float*)d_in[4];
    const float* Wv    = (const float*)d_in[5];
    const float* Wo    = (const float*)d_in[6];
    const float* W1    = (const float*)d_in[7];
    const float* b1    = (const float*)d_in[8];
    const float* W2    = (const float*)d_in[9];
    const float* b2    = (const float*)d_in[10];

    float *zp, *qp, *kp, *vp, *op, *anp, *ffp;
    cudaGetSymbolAddress((void**)&zp,  g_z);
    cudaGetSymbolAddress((void**)&qp,  g_q);
    cudaGetSymbolAddress((void**)&kp,  g_k);
    cudaGetSymbolAddress((void**)&vp,  g_v);
    cudaGetSymbolAddress((void**)&op,  g_o);
    cudaGetSymbolAddress((void**)&anp, g_an);
    cudaGetSymbolAddress((void**)&ffp, g_ff);

    embed_kernel<<<(NN * EE / 4) / 256, 256>>>(ctx, table, pos);

    for (int l = 0; l < NL; l++) {
        const float* wq = Wq + (size_t)l * NH * EE * VV;
        const float* wk = Wk + (size_t)l * NH * EE * VV;
        const float* wv = Wv + (size_t)l * NH * EE * VV;
        const float* wo = Wo + (size_t)l * HVD * EE;
        const float* w1 = W1 + (size_t)l * EE * FFD;
        const float* bb1 = b1 + (size_t)l * FFD;
        const float* w2 = W2 + (size_t)l * FFD * EE;
        const float* bb2 = b2 + (size_t)l * EE;

        dim3 gqkv(HVD / 64, NN / 64);
        gemm_kernel<0><<<gqkv, 256>>>(zp, wq, nullptr, nullptr, qp, NN, EE, HVD);
        gemm_kernel<0><<<gqkv, 256>>>(zp, wk, nullptr, nullptr, kp, NN, EE, HVD);
        gemm_kernel<0><<<gqkv, 256>>>(zp, wv, nullptr, nullptr, vp, NN, EE, HVD);

        attn_kernel<<<dim3(NN / 128, NH), 128>>>(qp, kp, vp, op);

        gemm_kernel<1><<<dim3(EE / 64, NN / 64), 256>>>(op, wo, nullptr, zp, anp, NN, HVD, EE);
        ln_kernel<<<NN, 256>>>(anp);

        gemm_kernel<2><<<dim3(FFD / 64, NN / 64), 256>>>(anp, w1, bb1, nullptr, ffp, NN, EE, FFD);
        gemm_kernel<3><<<dim3(EE / 64, NN / 64), 256>>>(ffp, w2, bb2, anp, zp, NN, FFD, EE);
        ln_kernel<<<NN, 256>>>(zp);
    }

    cudaMemcpyAsync(d_out, zp, sizeof(float) * NN * EE,
                    cudaMemcpyDeviceToDevice, 0);
}

// round 14
// speedup vs baseline: 1.1157x; 1.1157x over previous
#include <cuda_runtime.h>
#include <cstdint>

#define NL 6
#define NH 16
#define EE 1024
#define VV 32
#define NN 4096
#define HVD 512     // NH*VV
#define FFD 2048    // 2*EE

// ---------------- scratch (device globals; allocation-free) ----------------
__device__ float g_z[NN * EE];        // residual stream          16 MB
__device__ float g_q[NH * NN * VV];   // Q  [H][N][V]              8 MB
__device__ float g_k[NH * NN * VV];   // K                         8 MB
__device__ float g_v[NH * NN * VV];   // V                         8 MB
__device__ float g_o[NN * HVD];       // attn out [N][H*V]         8 MB
__device__ float g_an[NN * EE];       // post-attn LN             16 MB
__device__ float g_ff[NN * FFD];      // FF hidden                32 MB

// ---------------- fast exp on FMA pipe ------------------------------------
__device__ __forceinline__ float fexp(float x) {
    float t = fmaxf(x * 1.4426950408889634f, -126.0f);
    float fi = floorf(t);
    float f = t - fi;
    float p = 1.5403530e-4f;
    p = fmaf(p, f, 1.3333558e-3f);
    p = fmaf(p, f, 9.6181291e-3f);
    p = fmaf(p, f, 5.5504109e-2f);
    p = fmaf(p, f, 2.4022651e-1f);
    p = fmaf(p, f, 6.9314718e-1f);
    p = fmaf(p, f, 1.0f);
    return p * __int_as_float(((int)fi + 127) << 23);
}

// ---------------- embedding ------------------------------------------------
__global__ void __launch_bounds__(256) embed_kernel(const int* __restrict__ ctx,
                                                    const float* __restrict__ table,
                                                    const float* __restrict__ pos) {
    int idx = blockIdx.x * 256 + threadIdx.x;
    int n = idx >> 8;
    int e4 = idx & 255;
    int tok = ctx[n];
    float4 a = ((const float4*)table)[(size_t)tok * 256 + e4];
    float4 b = ((const float4*)pos)[idx];
    a.x += b.x; a.y += b.y; a.z += b.z; a.w += b.w;
    ((float4*)g_z)[idx] = a;
}

// ========================================================================
// 128x128 SGEMM core: 256 threads, 8x8 micro-tile, double-buffered smem.
// Per k-step: 64 FMA per thread vs 64 smem bytes -> FMA-bound (vs old 2x
// smem-bound 64x64/4x4 version measured at fma=37%, L1=75%).
// ========================================================================

struct GemmSmem {
    float As[2][8][132];   // [buf][k][m], pad 132 -> conflict-free transpose
    float Bs[2][8][128];   // [buf][k][n]
};

// MODE 1: C = resid + A*B              (A: MxK row-major, B: KxN row-major)
// MODE 2: C = leaky_relu(A*B + bias)
// MODE 3: C = resid + A*B + bias
template <int MODE>
__global__ void __launch_bounds__(256, 2) gemm_kernel(const float* __restrict__ A,
                                                      const float* __restrict__ B,
                                                      const float* __restrict__ bias,
                                                      const float* __restrict__ resid,
                                                      float* __restrict__ C,
                                                      int M, int K, int NC) {
    __shared__ GemmSmem sm;
    const int t  = threadIdx.x;
    const int tx = t & 15, ty = t >> 4;
    const int row0 = blockIdx.y << 7, col0 = blockIdx.x << 7;

    const int am = t >> 1, ak = (t & 1) << 2;     // A: 128 rows x 8 k
    const int bk = t >> 5, bn = (t & 31) << 2;    // B: 8 k x 128 cols

    const float* Aptr = A + (size_t)(row0 + am) * K + ak;
    const float* Bptr = B + (size_t)bk * NC + col0 + bn;

    // preload tile 0
    float4 av = *(const float4*)(Aptr);
    float4 bv = *(const float4*)(Bptr);
    sm.As[0][ak + 0][am] = av.x;
    sm.As[0][ak + 1][am] = av.y;
    sm.As[0][ak + 2][am] = av.z;
    sm.As[0][ak + 3][am] = av.w;
    *(float4*)&sm.Bs[0][bk][bn] = bv;
    __syncthreads();

    float acc[8][8];
#pragma unroll
    for (int i = 0; i < 8; i++)
#pragma unroll
        for (int j = 0; j < 8; j++) acc[i][j] = 0.f;

    const int NKT = K >> 3;
    for (int kt = 0; kt < NKT; kt++) {
        const int cur = kt & 1, nxt = cur ^ 1;
        if (kt + 1 < NKT) {
            int kb = (kt + 1) << 3;
            av = *(const float4*)(Aptr + kb);
            bv = *(const float4*)(Bptr + (size_t)kb * NC);
        }
#pragma unroll
        for (int k = 0; k < 8; k++) {
            float4 a0 = *(const float4*)&sm.As[cur][k][ty * 8];
            float4 a1 = *(const float4*)&sm.As[cur][k][ty * 8 + 4];
            float4 b0 = *(const float4*)&sm.Bs[cur][k][tx * 8];
            float4 b1 = *(const float4*)&sm.Bs[cur][k][tx * 8 + 4];
            float ar[8] = {a0.x, a0.y, a0.z, a0.w, a1.x, a1.y, a1.z, a1.w};
            float br[8] = {b0.x, b0.y, b0.z, b0.w, b1.x, b1.y, b1.z, b1.w};
#pragma unroll
            for (int i = 0; i < 8; i++)
#pragma unroll
                for (int j = 0; j < 8; j++)
                    acc[i][j] = fmaf(ar[i], br[j], acc[i][j]);
        }
        if (kt + 1 < NKT) {
            sm.As[nxt][ak + 0][am] = av.x;
            sm.As[nxt][ak + 1][am] = av.y;
            sm.As[nxt][ak + 2][am] = av.z;
            sm.As[nxt][ak + 3][am] = av.w;
            *(float4*)&sm.Bs[nxt][bk][bn] = bv;
        }
        __syncthreads();
    }

    const int c0 = col0 + tx * 8;
    float4 bias0, bias1;
    if (MODE == 2 || MODE == 3) {
        bias0 = *(const float4*)&bias[c0];
        bias1 = *(const float4*)&bias[c0 + 4];
    }
#pragma unroll
    for (int i = 0; i < 8; i++) {
        int r = row0 + ty * 8 + i;
        size_t o = (size_t)r * NC + c0;
        float out[8];
#pragma unroll
        for (int j = 0; j < 8; j++) out[j] = acc[i][j];
        if (MODE == 1) {
            float4 r0 = *(const float4*)&resid[o];
            float4 r1 = *(const float4*)&resid[o + 4];
            out[0] += r0.x; out[1] += r0.y; out[2] += r0.z; out[3] += r0.w;
            out[4] += r1.x; out[5] += r1.y; out[6] += r1.z; out[7] += r1.w;
        } else if (MODE == 2) {
            float bb[8] = {bias0.x, bias0.y, bias0.z, bias0.w,
                           bias1.x, bias1.y, bias1.z, bias1.w};
#pragma unroll
            for (int j = 0; j < 8; j++) {
                float x = out[j] + bb[j];
                out[j] = x > 0.f ? x : 0.01f * x;
            }
        } else {  // MODE 3
            float4 r0 = *(const float4*)&resid[o];
            float4 r1 = *(const float4*)&resid[o + 4];
            float bb[8] = {bias0.x, bias0.y, bias0.z, bias0.w,
                           bias1.x, bias1.y, bias1.z, bias1.w};
            out[0] += r0.x + bb[0]; out[1] += r0.y + bb[1];
            out[2] += r0.z + bb[2]; out[3] += r0.w + bb[3];
            out[4] += r1.x + bb[4]; out[5] += r1.y + bb[5];
            out[6] += r1.z + bb[6]; out[7] += r1.w + bb[7];
        }
        float4 s0 = {out[0], out[1], out[2], out[3]};
        float4 s1 = {out[4], out[5], out[6], out[7]};
        *(float4*)&C[o] = s0;
        *(float4*)&C[o + 4] = s1;
    }
}

// Fused QKV GEMM: one launch, 384 blocks. B layout [H][E][32]; C [H][N][32].
// blockIdx.x: 0-3 -> Q cols 0-511, 4-7 -> K, 8-11 -> V.
__global__ void __launch_bounds__(256, 2) qkv_kernel(const float* __restrict__ A,
                                                     const float* __restrict__ WQ,
                                                     const float* __restrict__ WK,
                                                     const float* __restrict__ WV,
                                                     float* __restrict__ Qo,
                                                     float* __restrict__ Ko,
                                                     float* __restrict__ Vo) {
    __shared__ GemmSmem sm;
    const int t  = threadIdx.x;
    const int tx = t & 15, ty = t >> 4;
    const int sel = blockIdx.x >> 2;
    const int col0 = (blockIdx.x & 3) << 7;
    const int row0 = blockIdx.y << 7;
    const int K = EE, M = NN;

    const float* B = (sel == 0) ? WQ : (sel == 1) ? WK : WV;
    float*       C = (sel == 0) ? Qo : (sel == 1) ? Ko : Vo;

    const int am = t >> 1, ak = (t & 1) << 2;
    const int bk = t >> 5, bn = (t & 31) << 2;

    const float* Aptr = A + (size_t)(row0 + am) * K + ak;
    const int colB = col0 + bn;
    // head-interleaved: B[(col>>5)*K*32 + k*32 + (col&31)]
    const float* Bptr = B + (size_t)(colB >> 5) * K * 32 + (size_t)bk * 32 + (colB & 31);

    float4 av = *(const float4*)(Aptr);
    float4 bv = *(const float4*)(Bptr);
    sm.As[0][ak + 0][am] = av.x;
    sm.As[0][ak + 1][am] = av.y;
    sm.As[0][ak + 2][am] = av.z;
    sm.As[0][ak + 3][am] = av.w;
    *(float4*)&sm.Bs[0][bk][bn] = bv;
    __syncthreads();

    float acc[8][8];
#pragma unroll
    for (int i = 0; i < 8; i++)
#pragma unroll
        for (int j = 0; j < 8; j++) acc[i][j] = 0.f;

    const int NKT = K >> 3;
    for (int kt = 0; kt < NKT; kt++) {
        const int cur = kt & 1, nxt = cur ^ 1;
        if (kt + 1 < NKT) {
            int kb = (kt + 1) << 3;
            av = *(const float4*)(Aptr + kb);
            bv = *(const float4*)(Bptr + (size_t)kb * 32);
        }
#pragma unroll
        for (int k = 0; k < 8; k++) {
            float4 a0 = *(const float4*)&sm.As[cur][k][ty * 8];
            float4 a1 = *(const float4*)&sm.As[cur][k][ty * 8 + 4];
            float4 b0 = *(const float4*)&sm.Bs[cur][k][tx * 8];
            float4 b1 = *(const float4*)&sm.Bs[cur][k][tx * 8 + 4];
            float ar[8] = {a0.x, a0.y, a0.z, a0.w, a1.x, a1.y, a1.z, a1.w};
            float br[8] = {b0.x, b0.y, b0.z, b0.w, b1.x, b1.y, b1.z, b1.w};
#pragma unroll
            for (int i = 0; i < 8; i++)
#pragma unroll
                for (int j = 0; j < 8; j++)
                    acc[i][j] = fmaf(ar[i], br[j], acc[i][j]);
        }
        if (kt + 1 < NKT) {
            sm.As[nxt][ak + 0][am] = av.x;
            sm.As[nxt][ak + 1][am] = av.y;
            sm.As[nxt][ak + 2][am] = av.z;
            sm.As[nxt][ak + 3][am] = av.w;
            *(float4*)&sm.Bs[nxt][bk][bn] = bv;
        }
        __syncthreads();
    }

    // C[h][n][32]: 8-col chunk at 8-aligned offset never straddles a head
    const int c = col0 + tx * 8;
    const int head = c >> 5, coff = c & 31;
#pragma unroll
    for (int i = 0; i < 8; i++) {
        int r = row0 + ty * 8 + i;
        float* Cp = C + ((size_t)head * M + r) * 32 + coff;
        float4 s0 = {acc[i][0], acc[i][1], acc[i][2], acc[i][3]};
        float4 s1 = {acc[i][4], acc[i][5], acc[i][6], acc[i][7]};
        *(float4*)Cp = s0;
        *(float4*)(Cp + 4) = s1;
    }
}

// ---------------- flash attention (unchanged) ------------------------------
__global__ void __launch_bounds__(128) attn_kernel(const float* __restrict__ Q,
                                                   const float* __restrict__ K,
                                                   const float* __restrict__ V,
                                                   float* __restrict__ O) {
    __shared__ float Ks[128 * 32];
    __shared__ float Vs[128 * 32];
    const int h = blockIdx.y;
    const int q0 = blockIdx.x << 7;
    const int tid = threadIdx.x;

    const float* Qp = Q + ((size_t)h * NN + q0 + tid) * VV;
    float q[32];
#pragma unroll
    for (int d4 = 0; d4 < 8; d4++) {
        float4 qv = *(const float4*)(Qp + d4 * 4);
        const float sc = 0.17677669529663687f;   // 1/sqrt(32)
        q[d4 * 4 + 0] = qv.x * sc;
        q[d4 * 4 + 1] = qv.y * sc;
        q[d4 * 4 + 2] = qv.z * sc;
        q[d4 * 4 + 3] = qv.w * sc;
    }

    float m = -1e30f, l = 0.f;
    float acc[32];
#pragma unroll
    for (int d = 0; d < 32; d++) acc[d] = 0.f;

    const float4* K4 = (const float4*)(K + (size_t)h * NN * VV);
    const float4* V4 = (const float4*)(V + (size_t)h * NN * VV);

    for (int kt = 0; kt < NN; kt += 128) {
        __syncthreads();
        const float4* Kt = K4 + (size_t)kt * 8;
        const float4* Vt = V4 + (size_t)kt * 8;
#pragma unroll
        for (int i = 0; i < 8; i++) {
            ((float4*)Ks)[tid + i * 128] = Kt[tid + i * 128];
            ((float4*)Vs)[tid + i * 128] = Vt[tid + i * 128];
        }
        __syncthreads();

#pragma unroll 1
        for (int jc = 0; jc < 128; jc += 16) {
            float s[16];
#pragma unroll
            for (int j = 0; j < 16; j++) {
                float a0 = 0.f, a1 = 0.f, a2 = 0.f, a3 = 0.f;
                const float* kr = Ks + (jc + j) * 32;
#pragma unroll
                for (int d4 = 0; d4 < 8; d4++) {
                    float4 kk = *(const float4*)(kr + d4 * 4);
                    a0 = fmaf(q[d4 * 4 + 0], kk.x, a0);
                    a1 = fmaf(q[d4 * 4 + 1], kk.y, a1);
                    a2 = fmaf(q[d4 * 4 + 2], kk.z, a2);
                    a3 = fmaf(q[d4 * 4 + 3], kk.w, a3);
                }
                s[j] = (a0 + a1) + (a2 + a3);
            }
            float cmax = s[0];
#pragma unroll
            for (int j = 1; j < 16; j++) cmax = fmaxf(cmax, s[j]);
            float mn = fmaxf(m, cmax);
            float corr = fexp(m - mn);
            m = mn;
            l *= corr;
#pragma unroll
            for (int d = 0; d < 32; d++) acc[d] *= corr;
#pragma unroll
            for (int j = 0; j < 16; j++) {
                float p = fexp(s[j] - mn);
                l += p;
                const float* vr = Vs + (jc + j) * 32;
#pragma unroll
                for (int d4 = 0; d4 < 8; d4++) {
                    float4 vv = *(const float4*)(vr + d4 * 4);
                    acc[d4 * 4 + 0] = fmaf(p, vv.x, acc[d4 * 4 + 0]);
                    acc[d4 * 4 + 1] = fmaf(p, vv.y, acc[d4 * 4 + 1]);
                    acc[d4 * 4 + 2] = fmaf(p, vv.z, acc[d4 * 4 + 2]);
                    acc[d4 * 4 + 3] = fmaf(p, vv.w, acc[d4 * 4 + 3]);
                }
            }
        }
    }

    float inv = 1.f / l;
    float* Op = O + (size_t)(q0 + tid) * HVD + h * VV;
#pragma unroll
    for (int d4 = 0; d4 < 8; d4++) {
        float4 ov;
        ov.x = acc[d4 * 4 + 0] * inv;
        ov.y = acc[d4 * 4 + 1] * inv;
        ov.z = acc[d4 * 4 + 2] * inv;
        ov.w = acc[d4 * 4 + 3] * inv;
        *(float4*)(Op + d4 * 4) = ov;
    }
}

// ---------------- layernorm ------------------------------------------------
__device__ __forceinline__ float block_sum256(float v, float* sbuf) {
    int lane = threadIdx.x & 31, w = threadIdx.x >> 5;
#pragma unroll
    for (int o = 16; o > 0; o >>= 1) v += __shfl_xor_sync(0xffffffffu, v, o);
    if (lane == 0) sbuf[w] = v;
    __syncthreads();
    if (w == 0) {
        float x = (lane < 8) ? sbuf[lane] : 0.f;
#pragma unroll
        for (int o = 4; o > 0; o >>= 1) x += __shfl_xor_sync(0xffffffffu, x, o);
        if (lane == 0) sbuf[0] = x;
    }
    __syncthreads();
    float r = sbuf[0];
    __syncthreads();
    return r;
}

__global__ void __launch_bounds__(256) ln_kernel(float* __restrict__ X) {
    __shared__ float sbuf[8];
    const int tid = threadIdx.x;
    float* x = X + (size_t)blockIdx.x * EE;
    float v[4];
#pragma unroll
    for (int i = 0; i < 4; i++) v[i] = x[tid + i * 256];
    float s = (v[0] + v[1]) + (v[2] + v[3]);
    s = block_sum256(s, sbuf);
    float mean = s * (1.f / 1024.f);
    float ss = 0.f;
#pragma unroll
    for (int i = 0; i < 4; i++) {
        float d = v[i] - mean;
        ss = fmaf(d, d, ss);
    }
    ss = block_sum256(ss, sbuf);
    float inv = rsqrtf(ss * (1.f / 1023.f));
#pragma unroll
    for (int i = 0; i < 4; i++) x[tid + i * 256] = (v[i] - mean) * inv;
}

// ---------------- launch ---------------------------------------------------
extern "C" void kernel_launch(void* const* d_in, const int* in_sizes, int n_in,
                              void* d_out, int out_size) {
    const int*   ctx   = (const int*)d_in[0];
    const float* table = (const float*)d_in[1];
    const float* pos   = (const float*)d_in[2];
    const float* Wq    = (const float*)d_in[3];
    const float* Wk    = (const float*)d_in[4];
    const float* Wv    = (const float*)d_in[5];
    const float* Wo    = (const float*)d_in[6];
    const float* W1    = (const float*)d_in[7];
    const float* b1    = (const float*)d_in[8];
    const float* W2    = (const float*)d_in[9];
    const float* b2    = (const float*)d_in[10];

    float *zp, *qp, *kp, *vp, *op, *anp, *ffp;
    cudaGetSymbolAddress((void**)&zp,  g_z);
    cudaGetSymbolAddress((void**)&qp,  g_q);
    cudaGetSymbolAddress((void**)&kp,  g_k);
    cudaGetSymbolAddress((void**)&vp,  g_v);
    cudaGetSymbolAddress((void**)&op,  g_o);
    cudaGetSymbolAddress((void**)&anp, g_an);
    cudaGetSymbolAddress((void**)&ffp, g_ff);

    embed_kernel<<<(NN * EE / 4) / 256, 256>>>(ctx, table, pos);

    for (int l = 0; l < NL; l++) {
        const float* wq = Wq + (size_t)l * NH * EE * VV;
        const float* wk = Wk + (size_t)l * NH * EE * VV;
        const float* wv = Wv + (size_t)l * NH * EE * VV;
        const float* wo = Wo + (size_t)l * HVD * EE;
        const float* w1 = W1 + (size_t)l * EE * FFD;
        const float* bb1 = b1 + (size_t)l * FFD;
        const float* w2 = W2 + (size_t)l * FFD * EE;
        const float* bb2 = b2 + (size_t)l * EE;

        qkv_kernel<<<dim3(12, NN / 128), 256>>>(zp, wq, wk, wv, qp, kp, vp);

        attn_kernel<<<dim3(NN / 128, NH), 128>>>(qp, kp, vp, op);

        gemm_kernel<1><<<dim3(EE / 128, NN / 128), 256>>>(op, wo, nullptr, zp, anp, NN, HVD, EE);
        ln_kernel<<<NN, 256>>>(anp);

        gemm_kernel<2><<<dim3(FFD / 128, NN / 128), 256>>>(anp, w1, bb1, nullptr, ffp, NN, EE, FFD);
        gemm_kernel<3><<<dim3(EE / 128, NN / 128), 256>>>(ffp, w2, bb2, anp, zp, NN, FFD, EE);
        ln_kernel<<<NN, 256>>>(zp);
    }

    cudaMemcpyAsync(d_out, zp, sizeof(float) * NN * EE,
                    cudaMemcpyDeviceToDevice, 0);
}